// round 1
// baseline (speedup 1.0000x reference)
#include <cuda_runtime.h>

#define NUM_TREES 256
#define DEPTH 6
#define INPUT_DIM 256
#define BATCH 2048
#define NCOLS (NUM_TREES * DEPTH)   // 1536
#define MAXNZ 256                    // worst-case sparsemax support
#define BCHUNKS 4

// Scratch (no cudaMalloc allowed)
__device__ float g_inT[INPUT_DIM * BATCH];   // 2 MB, inputs transposed
__device__ int   g_idx[NCOLS * MAXNZ];       // compacted selector indices
__device__ float g_wv [NCOLS * MAXNZ];       // compacted selector weights
__device__ int   g_nnz[NCOLS];

// ---------------------------------------------------------------------------
// Kernel A: transpose inputs [BATCH, INPUT_DIM] -> g_inT [INPUT_DIM, BATCH]
// ---------------------------------------------------------------------------
__global__ void transpose_kernel(const float* __restrict__ in) {
    __shared__ float tile[32][33];
    int bx = blockIdx.x * 32;   // input-dim tile base
    int by = blockIdx.y * 32;   // batch tile base
    int x = bx + threadIdx.x;
    #pragma unroll
    for (int i = 0; i < 32; i += 8) {
        int y = by + threadIdx.y + i;
        tile[threadIdx.y + i][threadIdx.x] = in[y * INPUT_DIM + x];
    }
    __syncthreads();
    int ox = by + threadIdx.x;  // batch index (contiguous on store)
    #pragma unroll
    for (int i = 0; i < 32; i += 8) {
        int oy = bx + threadIdx.y + i;  // input-dim index
        g_inT[oy * BATCH + ox] = tile[threadIdx.x][threadIdx.y + i];
    }
}

// ---------------------------------------------------------------------------
// Kernel B: exact sparsemax per (tree,depth) column + sparse compaction.
// One block of 256 threads per column; bitonic sort desc + inclusive scan.
// ---------------------------------------------------------------------------
__global__ void __launch_bounds__(256) sparsemax_kernel(const float* __restrict__ fsl) {
    const int col = blockIdx.x;     // n*DEPTH + d
    const int tid = threadIdx.x;

    __shared__ float xorig[INPUT_DIM];
    __shared__ float z[INPUT_DIM];
    __shared__ float cz[INPUT_DIM];
    __shared__ int   warpcnt[8];

    float x = fsl[tid * NCOLS + col];
    xorig[tid] = x;
    z[tid] = x;
    __syncthreads();

    // Bitonic sort, descending
    #pragma unroll
    for (int k = 2; k <= INPUT_DIM; k <<= 1) {
        for (int j = k >> 1; j > 0; j >>= 1) {
            int ixj = tid ^ j;
            if (ixj > tid) {
                float a = z[tid], b = z[ixj];
                bool desc = ((tid & k) == 0);
                if (desc ? (a < b) : (a > b)) { z[tid] = b; z[ixj] = a; }
            }
            __syncthreads();
        }
    }

    // Inclusive scan (cumsum) of sorted values
    float v = z[tid];
    cz[tid] = v;
    __syncthreads();
    #pragma unroll
    for (int off = 1; off < INPUT_DIM; off <<= 1) {
        float t = (tid >= off) ? cz[tid - off] : 0.0f;
        __syncthreads();
        cz[tid] += t;
        __syncthreads();
    }

    // Support size: count of k where 1 + k*z_k > cz_k  (k = tid+1)
    float zk = z[tid], czk = cz[tid];
    int ksel = __syncthreads_count((1.0f + (float)(tid + 1) * zk) > czk);
    float tau = (cz[ksel - 1] - 1.0f) / (float)ksel;

    // Compact nonzeros deterministically (index order)
    float w = xorig[tid] - tau;
    bool nz = (w > 0.0f);
    unsigned m = __ballot_sync(0xffffffffu, nz);
    int lane = tid & 31, warp = tid >> 5;
    if (lane == 0) warpcnt[warp] = __popc(m);
    __syncthreads();
    int base = 0;
    #pragma unroll
    for (int wi = 0; wi < 8; wi++) if (wi < warp) base += warpcnt[wi];
    if (nz) {
        int pos = base + __popc(m & ((1u << lane) - 1u));
        g_idx[col * MAXNZ + pos] = tid;
        g_wv [col * MAXNZ + pos] = w;
    }
    if (tid == 0) {
        int tot = 0;
        #pragma unroll
        for (int wi = 0; wi < 8; wi++) tot += warpcnt[wi];
        g_nnz[col] = tot;
    }
}

// ---------------------------------------------------------------------------
// Kernel C: fused feature-gather + binning + product tree + response dot.
// Block = (tree n, batch chunk). 256 threads, each thread owns batch rows.
// ---------------------------------------------------------------------------
__global__ void __launch_bounds__(256) odt_main(
    const float* __restrict__ thr,    // [NUM_TREES, DEPTH]
    const float* __restrict__ logT,   // [NUM_TREES, DEPTH]
    const float* __restrict__ resp,   // [NUM_TREES, 2, 64]
    float* __restrict__ out)          // [BATCH, NUM_TREES*2]
{
    const int n = blockIdx.x;
    const int bchunk = blockIdx.y;
    const int tid = threadIdx.x;

    __shared__ int   s_nnz[DEPTH];
    __shared__ float s_thr[DEPTH], s_invT[DEPTH];
    __shared__ float s_resp[2 * 64];
    __shared__ int   s_idx[DEPTH][MAXNZ];
    __shared__ float s_w  [DEPTH][MAXNZ];

    if (tid < DEPTH) {
        s_nnz[tid]  = g_nnz[n * DEPTH + tid];
        s_thr[tid]  = thr[n * DEPTH + tid];
        s_invT[tid] = expf(-logT[n * DEPTH + tid]);
    }
    if (tid < 128) s_resp[tid] = resp[n * 128 + tid];
    __syncthreads();

    #pragma unroll
    for (int d = 0; d < DEPTH; d++) {
        int nn = s_nnz[d];
        int cb = (n * DEPTH + d) * MAXNZ;
        for (int j = tid; j < nn; j += 256) {
            s_idx[d][j] = g_idx[cb + j];
            s_w  [d][j] = g_wv [cb + j];
        }
    }
    __syncthreads();

    const int rows = BATCH / BCHUNKS;      // 512
    for (int r = 0; r < rows; r += 256) {
        int b = bchunk * rows + r + tid;   // coalesced across warp

        // Sparse gather-dot: fv[d] = sum_j inputs[b, idx] * w
        float p[DEPTH];
        #pragma unroll
        for (int d = 0; d < DEPTH; d++) {
            float s = 0.0f;
            int nn = s_nnz[d];
            for (int j = 0; j < nn; j++)
                s = fmaf(g_inT[s_idx[d][j] * BATCH + b], s_w[d][j], s);
            float t = fmaf(s - s_thr[d], 0.5f * s_invT[d], 0.5f);
            p[d] = fminf(fmaxf(t, 0.0f), 1.0f);   // sparsemoid(tl); other bin = 1-p
        }

        // Leaf weights: w[c] = prod_d (bit_d(c) ? (1-p_d) : p_d)
        float w[64];
        w[0] = 1.0f;
        #pragma unroll
        for (int d = 0; d < DEPTH; d++) {
            float q0 = p[d], q1 = 1.0f - p[d];
            #pragma unroll
            for (int c = (1 << d) - 1; c >= 0; c--) {
                float ww = w[c];
                w[c | (1 << d)] = ww * q1;
                w[c]            = ww * q0;
            }
        }

        // Response dot
        float o0 = 0.0f, o1 = 0.0f;
        #pragma unroll
        for (int c = 0; c < 64; c++) {
            o0 = fmaf(w[c], s_resp[c],      o0);
            o1 = fmaf(w[c], s_resp[64 + c], o1);
        }
        out[b * (NUM_TREES * 2) + 2 * n]     = o0;
        out[b * (NUM_TREES * 2) + 2 * n + 1] = o1;
    }
}

// ---------------------------------------------------------------------------
extern "C" void kernel_launch(void* const* d_in, const int* in_sizes, int n_in,
                              void* d_out, int out_size) {
    const float* inputs = (const float*)d_in[0];
    const float* fsl    = (const float*)d_in[1];
    const float* thr    = (const float*)d_in[2];
    const float* logT   = (const float*)d_in[3];
    const float* resp   = (const float*)d_in[4];
    float* out = (float*)d_out;

    dim3 tb(32, 8);
    dim3 tg(INPUT_DIM / 32, BATCH / 32);
    transpose_kernel<<<tg, tb>>>(inputs);

    sparsemax_kernel<<<NCOLS, 256>>>(fsl);

    dim3 mg(NUM_TREES, BCHUNKS);
    odt_main<<<mg, 256>>>(thr, logT, resp, out);
}

// round 2
// speedup vs baseline: 3.1717x; 3.1717x over previous
#include <cuda_runtime.h>

#define NUM_TREES 256
#define DEPTH 6
#define INPUT_DIM 256
#define BATCH 2048
#define NCOLS (NUM_TREES * DEPTH)   // 1536
#define MAXNZ 256
#define OUTW (NUM_TREES * 2)        // 512

// Device scratch (no cudaMalloc allowed)
__device__ float  g_inT [INPUT_DIM * BATCH];    // 2 MB   inputs^T  [i][b]
__device__ float  g_fslT[NCOLS * INPUT_DIM];    // 1.5 MB fsl^T     [col][i]
__device__ float2 g_pack[NCOLS * MAXNZ];        // 3 MB   {idx-bits, weight}
__device__ int    g_nnz [NCOLS];                // padded (multiple of 4)

// ---------------------------------------------------------------------------
// Kernel A: fused transposes.
//   inputs [2048 x 256] -> g_inT [256 x 2048]      tiles: 8 x 64 = 512 blocks
//   fsl    [256 x 1536] -> g_fslT [1536 x 256]     tiles: 48 x 8 = 384 blocks
// ---------------------------------------------------------------------------
__global__ void __launch_bounds__(256) transpose2_kernel(
    const float* __restrict__ inputs, const float* __restrict__ fsl)
{
    __shared__ float tile[32][33];
    int blk = blockIdx.x;
    const float* src; float* dst; int R, C, tx, ty;
    if (blk < 512) { src = inputs; dst = g_inT;  R = BATCH; C = INPUT_DIM;
                     tx = blk % (INPUT_DIM/32); ty = blk / (INPUT_DIM/32); }
    else { blk -= 512; src = fsl; dst = g_fslT;  R = INPUT_DIM; C = NCOLS;
           tx = blk % (NCOLS/32); ty = blk / (NCOLS/32); }

    int x = tx * 32 + threadIdx.x;
    #pragma unroll
    for (int i = 0; i < 32; i += 8) {
        int y = ty * 32 + threadIdx.y + i;
        tile[threadIdx.y + i][threadIdx.x] = src[(size_t)y * C + x];
    }
    __syncthreads();
    int ox = ty * 32 + threadIdx.x;
    #pragma unroll
    for (int i = 0; i < 32; i += 8) {
        int oy = tx * 32 + threadIdx.y + i;
        dst[(size_t)oy * R + ox] = tile[threadIdx.x][threadIdx.y + i];
    }
}

// ---------------------------------------------------------------------------
// Kernel B: exact sparsemax per column via Michelot fixed-point (warp/column),
// then deterministic compaction + pad-to-4. No block barriers at all.
// ---------------------------------------------------------------------------
__global__ void __launch_bounds__(256) sparsemax_michelot(void)
{
    const int warp = threadIdx.x >> 5;
    const int lane = threadIdx.x & 31;
    const int col  = blockIdx.x * 8 + warp;      // 192 blocks x 8 warps = 1536

    // 8 values per lane, coalesced
    float v[8];
    #pragma unroll
    for (int j = 0; j < 8; j++)
        v[j] = g_fslT[col * INPUT_DIM + j * 32 + lane];

    // initial tau from full support
    float s = v[0];
    #pragma unroll
    for (int j = 1; j < 8; j++) s += v[j];
    #pragma unroll
    for (int o = 16; o > 0; o >>= 1) s += __shfl_xor_sync(0xffffffffu, s, o);
    float tau = (s - 1.0f) / 256.0f;

    // fixed point: S <- {v > tau}, tau <- (sum(S)-1)/|S|; support shrinks
    int cprev = 256;
    for (int it = 0; it < 64; it++) {
        float ps = 0.0f; int pc = 0;
        #pragma unroll
        for (int j = 0; j < 8; j++)
            if (v[j] > tau) { ps += v[j]; pc++; }
        #pragma unroll
        for (int o = 16; o > 0; o >>= 1) {
            ps += __shfl_xor_sync(0xffffffffu, ps, o);
            pc += __shfl_xor_sync(0xffffffffu, pc, o);
        }
        tau = (ps - 1.0f) / (float)pc;
        if (pc == cprev) break;
        cprev = pc;
    }

    // compaction in index order; pad to multiple of 4 with zero weights
    const unsigned ltmask = (1u << lane) - 1u;
    int total = 0;
    #pragma unroll
    for (int j = 0; j < 8; j++) {
        float w = v[j] - tau;
        bool nz = (w > 0.0f);
        unsigned m = __ballot_sync(0xffffffffu, nz);
        if (nz) {
            int pos = total + __popc(m & ltmask);
            g_pack[col * MAXNZ + pos] =
                make_float2(__int_as_float(j * 32 + lane), w);
        }
        total += __popc(m);
    }
    int tot4 = (total + 3) & ~3;
    if (lane < tot4 - total)
        g_pack[col * MAXNZ + total + lane] = make_float2(__int_as_float(0), 0.0f);
    if (lane == 0) g_nnz[col] = tot4;
}

// ---------------------------------------------------------------------------
// Response contraction: out = sum_c R[c] * prod_d (bit_d(c) ? 1-p_d : p_d)
// contracted LSB-first; peak 32 temps.
// ---------------------------------------------------------------------------
__device__ __forceinline__ float contract64(const float* __restrict__ r,
                                            const float p[DEPTH])
{
    float t[32];
    #pragma unroll
    for (int k = 0; k < 32; k++) {
        float a = r[2*k], b = r[2*k+1];
        t[k] = fmaf(p[0], a - b, b);
    }
    #pragma unroll
    for (int d = 1; d < DEPTH; d++) {
        #pragma unroll
        for (int k = 0; k < 32; k++) {
            if (k < (32 >> d)) {
                float a = t[2*k], b = t[2*k+1];
                t[k] = fmaf(p[d], a - b, b);
            }
        }
    }
    return t[0];
}

// ---------------------------------------------------------------------------
// Kernel C: fused sparse-gather + binning + response contraction.
// Block = (tree n, batch-chunk of 512). Each thread handles 2 batch rows.
// ---------------------------------------------------------------------------
__global__ void __launch_bounds__(256) odt_main(
    const float* __restrict__ thr,
    const float* __restrict__ logT,
    const float* __restrict__ resp,
    float* __restrict__ out)
{
    const int n   = blockIdx.x;
    const int tid = threadIdx.x;

    __shared__ float s_resp[2 * 64];
    __shared__ int   s_nnz[DEPTH];
    __shared__ float s_thr[DEPTH], s_hiT[DEPTH];

    if (tid < 128) s_resp[tid] = resp[n * 128 + tid];
    if (tid < DEPTH) {
        s_nnz[tid] = g_nnz[n * DEPTH + tid];
        s_thr[tid] = thr [n * DEPTH + tid];
        s_hiT[tid] = 0.5f * expf(-logT[n * DEPTH + tid]);
    }
    __syncthreads();

    const int b0 = blockIdx.y * 512 + tid;
    const int b1 = b0 + 256;

    float pA[DEPTH], pB[DEPTH];
    #pragma unroll
    for (int d = 0; d < DEPTH; d++) {
        const float2* __restrict__ pk = g_pack + (size_t)(n * DEPTH + d) * MAXNZ;
        const int nn = s_nnz[d];
        float a0 = 0.0f, a1 = 0.0f;
        for (int j = 0; j < nn; j += 4) {
            float2 q0 = __ldg(pk + j);
            float2 q1 = __ldg(pk + j + 1);
            float2 q2 = __ldg(pk + j + 2);
            float2 q3 = __ldg(pk + j + 3);
            int i0 = __float_as_int(q0.x), i1 = __float_as_int(q1.x);
            int i2 = __float_as_int(q2.x), i3 = __float_as_int(q3.x);
            float x00 = g_inT[i0 * BATCH + b0], x01 = g_inT[i0 * BATCH + b1];
            float x10 = g_inT[i1 * BATCH + b0], x11 = g_inT[i1 * BATCH + b1];
            float x20 = g_inT[i2 * BATCH + b0], x21 = g_inT[i2 * BATCH + b1];
            float x30 = g_inT[i3 * BATCH + b0], x31 = g_inT[i3 * BATCH + b1];
            a0 = fmaf(x00, q0.y, a0);  a1 = fmaf(x01, q0.y, a1);
            a0 = fmaf(x10, q1.y, a0);  a1 = fmaf(x11, q1.y, a1);
            a0 = fmaf(x20, q2.y, a0);  a1 = fmaf(x21, q2.y, a1);
            a0 = fmaf(x30, q3.y, a0);  a1 = fmaf(x31, q3.y, a1);
        }
        float tA = fmaf(a0 - s_thr[d], s_hiT[d], 0.5f);
        float tB = fmaf(a1 - s_thr[d], s_hiT[d], 0.5f);
        pA[d] = fminf(fmaxf(tA, 0.0f), 1.0f);
        pB[d] = fminf(fmaxf(tB, 0.0f), 1.0f);
    }

    float2 oA, oB;
    oA.x = contract64(s_resp,      pA);
    oA.y = contract64(s_resp + 64, pA);
    oB.x = contract64(s_resp,      pB);
    oB.y = contract64(s_resp + 64, pB);

    *(float2*)(out + (size_t)b0 * OUTW + 2 * n) = oA;
    *(float2*)(out + (size_t)b1 * OUTW + 2 * n) = oB;
}

// ---------------------------------------------------------------------------
extern "C" void kernel_launch(void* const* d_in, const int* in_sizes, int n_in,
                              void* d_out, int out_size) {
    const float* inputs = (const float*)d_in[0];
    const float* fsl    = (const float*)d_in[1];
    const float* thr    = (const float*)d_in[2];
    const float* logT   = (const float*)d_in[3];
    const float* resp   = (const float*)d_in[4];
    float* out = (float*)d_out;

    transpose2_kernel<<<512 + 384, dim3(32, 8)>>>(inputs, fsl);
    sparsemax_michelot<<<NCOLS / 8, 256>>>();
    dim3 mg(NUM_TREES, BATCH / 512);
    odt_main<<<mg, 256>>>(thr, logT, resp, out);
}

// round 3
// speedup vs baseline: 3.4553x; 1.0894x over previous
#include <cuda_runtime.h>

#define NUM_TREES 256
#define DEPTH 6
#define INPUT_DIM 256
#define BATCH 2048
#define NCOLS (NUM_TREES * DEPTH)   // 1536
#define MAXNZ 256
#define OUTW (NUM_TREES * 2)        // 512
#define PCAP 32                      // smem-cached pack entries per column
#define TPAD 66                      // padded batch-tile row stride (floats)

// Device scratch
__device__ float2 g_pack[NCOLS * MAXNZ];     // {idx-bits, weight}, padded to x4
__device__ int    g_nnz [NCOLS];
__device__ float  g_coef[NUM_TREES * 64 * 2]; // multilinear coeffs [n][c][tdim]

// packed fp32x2 FMA (Blackwell)
__device__ __forceinline__ float2 fma2(float2 a, float2 b, float2 c) {
    unsigned long long A, B, C, R;
    A = *reinterpret_cast<unsigned long long*>(&a);
    B = *reinterpret_cast<unsigned long long*>(&b);
    C = *reinterpret_cast<unsigned long long*>(&c);
    asm("fma.rn.f32x2 %0, %1, %2, %3;" : "=l"(R) : "l"(A), "l"(B), "l"(C));
    return *reinterpret_cast<float2*>(&R);
}

// ---------------------------------------------------------------------------
// Prep kernel: blocks 0..191  = sparsemax (8 columns each, Michelot) + compact
//              blocks 192..255 = response -> multilinear coefficient transform
// ---------------------------------------------------------------------------
__global__ void __launch_bounds__(256) prep_kernel(
    const float* __restrict__ fsl, const float* __restrict__ resp)
{
    const int tid  = threadIdx.x;
    const int warp = tid >> 5;
    const int lane = tid & 31;

    if (blockIdx.x < 192) {
        // ---- sparsemax over 8 columns ----
        __shared__ float s[INPUT_DIM * 9];   // [row][col] pad 9
        const int colBase = blockIdx.x * 8;
        #pragma unroll
        for (int k = 0; k < 8; k++) {
            int linear = k * 256 + tid;
            int r = linear >> 3, c = linear & 7;
            s[r * 9 + c] = fsl[r * NCOLS + colBase + c];
        }
        __syncthreads();

        const int col = colBase + warp;
        float v[8];
        #pragma unroll
        for (int j = 0; j < 8; j++) v[j] = s[(j * 32 + lane) * 9 + warp];

        float ss = v[0];
        #pragma unroll
        for (int j = 1; j < 8; j++) ss += v[j];
        #pragma unroll
        for (int o = 16; o > 0; o >>= 1) ss += __shfl_xor_sync(~0u, ss, o);
        float tau = (ss - 1.0f) / 256.0f;

        int cprev = 256;
        for (int it = 0; it < 64; it++) {
            float ps = 0.0f; int pc = 0;
            #pragma unroll
            for (int j = 0; j < 8; j++)
                if (v[j] > tau) { ps += v[j]; pc++; }
            #pragma unroll
            for (int o = 16; o > 0; o >>= 1) {
                ps += __shfl_xor_sync(~0u, ps, o);
                pc += __shfl_xor_sync(~0u, pc, o);
            }
            tau = (ps - 1.0f) / (float)pc;
            if (pc == cprev) break;
            cprev = pc;
        }

        const unsigned ltmask = (1u << lane) - 1u;
        int total = 0;
        #pragma unroll
        for (int j = 0; j < 8; j++) {
            float w = v[j] - tau;
            bool nz = (w > 0.0f);
            unsigned m = __ballot_sync(~0u, nz);
            if (nz) {
                int pos = total + __popc(m & ltmask);
                g_pack[col * MAXNZ + pos] =
                    make_float2(__int_as_float(j * 32 + lane), w);
            }
            total += __popc(m);
        }
        int tot4 = (total + 3) & ~3;
        if (lane < tot4 - total)
            g_pack[col * MAXNZ + total + lane] = make_float2(__int_as_float(0), 0.0f);
        if (lane == 0) g_nnz[col] = tot4;
    } else {
        // ---- coefficient transform: warp = (tree, tdim) ----
        const int cb = blockIdx.x - 192;
        const int n  = cb * 4 + (warp >> 1);
        const int t  = warp & 1;
        float r0 = resp[(n * 2 + t) * 64 + lane];
        float r1 = resp[(n * 2 + t) * 64 + 32 + lane];
        #pragma unroll
        for (int d = 0; d < 5; d++) {
            int m = 1 << d;
            float o0 = __shfl_xor_sync(~0u, r0, m);
            float o1 = __shfl_xor_sync(~0u, r1, m);
            bool hi = (lane >> d) & 1;
            r0 = hi ? (o0 - r0) : o0;   // bit=0 slot: const=A1; bit=1: lin=A0-A1
            r1 = hi ? (o1 - r1) : o1;
        }
        { float tmp = r0; r0 = r1; r1 = tmp - r1; }   // d=5 across regs
        g_coef[(n * 64 + lane)      * 2 + t] = r0;
        g_coef[(n * 64 + 32 + lane) * 2 + t] = r1;
    }
}

// ---------------------------------------------------------------------------
// Main kernel: block = (tree group of 32, batch tile of 64 rows), 512 threads.
// sub = tid>>5 owns 2 trees; lane owns a batch row-pair (b0=2*lane, b1=+1).
// ---------------------------------------------------------------------------
__global__ void __launch_bounds__(512) odt_main(
    const float* __restrict__ inputs,
    const float* __restrict__ thr,
    const float* __restrict__ logT,
    float* __restrict__ out)
{
    extern __shared__ __align__(16) char smem[];
    float*  s_in    = (float*) smem;                         // [256][66]
    float4* s_pack4 = (float4*)(smem + 67584);               // [192][16] (=32 f2)
    float4* s_coef4 = (float4*)(smem + 67584 + 49152);       // [32][32]
    int*    s_nnz   = (int*)   (smem + 67584 + 49152 + 16384);   // [192]
    float2* s_th    = (float2*)(smem + 67584 + 49152 + 16384 + 768); // [192]

    const int tid  = threadIdx.x;
    const int lane = tid & 31;
    const int sub  = tid >> 5;
    const int grp  = blockIdx.x;          // 0..7
    const int tileB = blockIdx.y * 64;    // batch tile base
    const int nBase = grp * 32;
    const int colBase = nBase * DEPTH;    // grp*192

    // stage input tile [256 i][64 b] transposed, pad 66
    #pragma unroll
    for (int e = 0; e < 32; e++) {
        int linear = e * 512 + tid;
        int i = linear & 255, b = linear >> 8;
        s_in[i * TPAD + b] = inputs[(tileB + b) * INPUT_DIM + i];
    }
    // stage packs (first 32 entries per column)
    const float4* gp4 = (const float4*)g_pack;
    #pragma unroll
    for (int q = 0; q < 6; q++) {
        int idx = q * 512 + tid;          // 3072 float4 total
        int cl = idx >> 4, j = idx & 15;
        s_pack4[cl * 16 + j] = gp4[(colBase + cl) * (MAXNZ / 2) + j];
    }
    // stage coefficients
    const float4* gc4 = (const float4*)g_coef;
    #pragma unroll
    for (int e = 0; e < 2; e++) {
        int idx = e * 512 + tid;          // 1024 float4
        s_coef4[idx] = gc4[nBase * 32 + idx];
    }
    // nnz + thresholds
    if (tid < 192) {
        int gcol = colBase + tid;
        s_nnz[tid] = g_nnz[gcol];
        s_th[tid]  = make_float2(thr[gcol], 0.5f * expf(-logT[gcol]));
    }
    __syncthreads();

    float2 res[2][2];   // [k][row]

    #pragma unroll
    for (int k = 0; k < 2; k++) {
        const int nL = sub * 2 + k;

        // p values for both rows
        float2 pp0[DEPTH], pp1[DEPTH];
        #pragma unroll
        for (int d = 0; d < DEPTH; d++) {
            const int colL = nL * DEPTH + d;
            const int nn = s_nnz[colL];
            const int nns = nn < PCAP ? nn : PCAP;
            float2 acc = make_float2(0.0f, 0.0f);
            const float4* pk = s_pack4 + colL * 16;
            for (int j = 0; j < nns; j += 4) {
                float4 a = pk[j >> 1];
                float4 b = pk[(j >> 1) + 1];
                int i0 = __float_as_int(a.x), i1 = __float_as_int(a.z);
                int i2 = __float_as_int(b.x), i3 = __float_as_int(b.z);
                float2 x0 = *(const float2*)(s_in + i0 * TPAD + 2 * lane);
                float2 x1 = *(const float2*)(s_in + i1 * TPAD + 2 * lane);
                float2 x2 = *(const float2*)(s_in + i2 * TPAD + 2 * lane);
                float2 x3 = *(const float2*)(s_in + i3 * TPAD + 2 * lane);
                acc = fma2(x0, make_float2(a.y, a.y), acc);
                acc = fma2(x1, make_float2(a.w, a.w), acc);
                acc = fma2(x2, make_float2(b.y, b.y), acc);
                acc = fma2(x3, make_float2(b.w, b.w), acc);
            }
            // rare fallback: support > PCAP
            for (int j = PCAP; j < nn; j += 4) {
                const float2* gq = g_pack + (colBase + colL) * MAXNZ + j;
                #pragma unroll
                for (int u = 0; u < 4; u++) {
                    float2 q = __ldg(gq + u);
                    int ii = __float_as_int(q.x);
                    float2 x = *(const float2*)(s_in + ii * TPAD + 2 * lane);
                    acc = fma2(x, make_float2(q.y, q.y), acc);
                }
            }
            float2 th = s_th[colL];
            float pA = fminf(fmaxf(fmaf(acc.x - th.x, th.y, 0.5f), 0.0f), 1.0f);
            float pB = fminf(fmaxf(fmaf(acc.y - th.x, th.y, 0.5f), 0.0f), 1.0f);
            pp0[d] = make_float2(pA, pA);
            pp1[d] = make_float2(pB, pB);
        }

        // multilinear evaluation, tdims packed, both rows share coef loads
        const float4* cf = s_coef4 + nL * 32;
        float2 w0[8], w1[8];
        #pragma unroll
        for (int j = 0; j < 8; j++) {
            float2 v0a, v0b, v1a, v1b;
            {
                float4 c0 = cf[4 * j + 0], c1 = cf[4 * j + 1];
                float2 lo0 = make_float2(c0.x, c0.y), hi0 = make_float2(c0.z, c0.w);
                float2 lo1 = make_float2(c1.x, c1.y), hi1 = make_float2(c1.z, c1.w);
                float2 u0r0 = fma2(pp0[0], hi0, lo0);
                float2 u0r1 = fma2(pp1[0], hi0, lo0);
                float2 u1r0 = fma2(pp0[0], hi1, lo1);
                float2 u1r1 = fma2(pp1[0], hi1, lo1);
                v0a = fma2(pp0[1], u1r0, u0r0);
                v1a = fma2(pp1[1], u1r1, u0r1);
            }
            {
                float4 c2 = cf[4 * j + 2], c3 = cf[4 * j + 3];
                float2 lo2 = make_float2(c2.x, c2.y), hi2 = make_float2(c2.z, c2.w);
                float2 lo3 = make_float2(c3.x, c3.y), hi3 = make_float2(c3.z, c3.w);
                float2 u2r0 = fma2(pp0[0], hi2, lo2);
                float2 u2r1 = fma2(pp1[0], hi2, lo2);
                float2 u3r0 = fma2(pp0[0], hi3, lo3);
                float2 u3r1 = fma2(pp1[0], hi3, lo3);
                v0b = fma2(pp0[1], u3r0, u2r0);
                v1b = fma2(pp1[1], u3r1, u2r1);
            }
            w0[j] = fma2(pp0[2], v0b, v0a);
            w1[j] = fma2(pp1[2], v1b, v1a);
        }
        float2 x0[4], x1[4];
        #pragma unroll
        for (int j = 0; j < 4; j++) {
            x0[j] = fma2(pp0[3], w0[2 * j + 1], w0[2 * j]);
            x1[j] = fma2(pp1[3], w1[2 * j + 1], w1[2 * j]);
        }
        float2 y00 = fma2(pp0[4], x0[1], x0[0]);
        float2 y01 = fma2(pp0[4], x0[3], x0[2]);
        float2 y10 = fma2(pp1[4], x1[1], x1[0]);
        float2 y11 = fma2(pp1[4], x1[3], x1[2]);
        res[k][0] = fma2(pp0[5], y01, y00);
        res[k][1] = fma2(pp1[5], y11, y10);
    }

    // store: 4 consecutive trees' (t0,t1) per row -> 16B aligned STG.128
    const int b0 = tileB + 2 * lane;
    float* o0 = out + (size_t)b0 * OUTW + grp * 64 + sub * 4;
    float* o1 = o0 + OUTW;
    *(float4*)o0 = make_float4(res[0][0].x, res[0][0].y, res[1][0].x, res[1][0].y);
    *(float4*)o1 = make_float4(res[0][1].x, res[0][1].y, res[1][1].x, res[1][1].y);
}

// ---------------------------------------------------------------------------
#define ODT_SMEM (67584 + 49152 + 16384 + 768 + 1536)

extern "C" void kernel_launch(void* const* d_in, const int* in_sizes, int n_in,
                              void* d_out, int out_size) {
    const float* inputs = (const float*)d_in[0];
    const float* fsl    = (const float*)d_in[1];
    const float* thr    = (const float*)d_in[2];
    const float* logT   = (const float*)d_in[3];
    const float* resp   = (const float*)d_in[4];
    float* out = (float*)d_out;

    cudaFuncSetAttribute(odt_main, cudaFuncAttributeMaxDynamicSharedMemorySize,
                         ODT_SMEM);

    prep_kernel<<<256, 256>>>(fsl, resp);
    odt_main<<<dim3(8, 32), 512, ODT_SMEM>>>(inputs, thr, logT, out);
}

// round 4
// speedup vs baseline: 3.7888x; 1.0965x over previous
#include <cuda_runtime.h>

#define NUM_TREES 256
#define DEPTH 6
#define INPUT_DIM 256
#define BATCH 2048
#define NCOLS (NUM_TREES * DEPTH)   // 1536
#define MAXNZ 256
#define OUTW (NUM_TREES * 2)        // 512
#define PCAP 16                      // smem-cached pack entries per column
#define TPAD 66                      // padded batch-tile row stride (floats)

// smem layout offsets (bytes)
#define OFF_PACK 67584
#define OFF_COEF (OFF_PACK + 24576)          // 92160
#define OFF_NNZ  (OFF_COEF + 16384)          // 108544
#define OFF_TH   (OFF_NNZ + 768)             // 109312
#define ODT_SMEM (OFF_TH + 1536)             // 110848

// Device scratch
__device__ float2 g_pack[NCOLS * MAXNZ];      // {idx-bits, weight}, padded to x4
__device__ int    g_nnz [NCOLS];
__device__ float  g_coef[NUM_TREES * 64 * 2]; // multilinear coeffs [n][c][tdim]

// packed fp32x2 FMA (Blackwell)
__device__ __forceinline__ float2 fma2(float2 a, float2 b, float2 c) {
    unsigned long long A, B, C, R;
    A = *reinterpret_cast<unsigned long long*>(&a);
    B = *reinterpret_cast<unsigned long long*>(&b);
    C = *reinterpret_cast<unsigned long long*>(&c);
    asm("fma.rn.f32x2 %0, %1, %2, %3;" : "=l"(R) : "l"(A), "l"(B), "l"(C));
    return *reinterpret_cast<float2*>(&R);
}

// ---------------------------------------------------------------------------
// Prep kernel: blocks 0..191  = sparsemax (8 columns each, Michelot) + compact
//              blocks 192..255 = response -> multilinear coefficient transform
// ---------------------------------------------------------------------------
__global__ void __launch_bounds__(256) prep_kernel(
    const float* __restrict__ fsl, const float* __restrict__ resp)
{
    const int tid  = threadIdx.x;
    const int warp = tid >> 5;
    const int lane = tid & 31;

    if (blockIdx.x < 192) {
        // ---- sparsemax over 8 columns ----
        __shared__ float s[INPUT_DIM * 9];   // [row][col] pad 9
        const int colBase = blockIdx.x * 8;
        #pragma unroll
        for (int k = 0; k < 8; k++) {
            int linear = k * 256 + tid;
            int r = linear >> 3, c = linear & 7;
            s[r * 9 + c] = fsl[r * NCOLS + colBase + c];
        }
        __syncthreads();

        const int col = colBase + warp;
        float v[8];
        #pragma unroll
        for (int j = 0; j < 8; j++) v[j] = s[(j * 32 + lane) * 9 + warp];

        float ss = v[0];
        #pragma unroll
        for (int j = 1; j < 8; j++) ss += v[j];
        #pragma unroll
        for (int o = 16; o > 0; o >>= 1) ss += __shfl_xor_sync(~0u, ss, o);
        float tau = (ss - 1.0f) / 256.0f;

        int cprev = 256;
        for (int it = 0; it < 64; it++) {
            float ps = 0.0f; int pc = 0;
            #pragma unroll
            for (int j = 0; j < 8; j++)
                if (v[j] > tau) { ps += v[j]; pc++; }
            #pragma unroll
            for (int o = 16; o > 0; o >>= 1) {
                ps += __shfl_xor_sync(~0u, ps, o);
                pc += __shfl_xor_sync(~0u, pc, o);
            }
            tau = (ps - 1.0f) / (float)pc;
            if (pc == cprev) break;
            cprev = pc;
        }

        const unsigned ltmask = (1u << lane) - 1u;
        int total = 0;
        #pragma unroll
        for (int j = 0; j < 8; j++) {
            float w = v[j] - tau;
            bool nz = (w > 0.0f);
            unsigned m = __ballot_sync(~0u, nz);
            if (nz) {
                int pos = total + __popc(m & ltmask);
                g_pack[col * MAXNZ + pos] =
                    make_float2(__int_as_float(j * 32 + lane), w);
            }
            total += __popc(m);
        }
        int tot4 = (total + 3) & ~3;
        if (lane < tot4 - total)
            g_pack[col * MAXNZ + total + lane] = make_float2(__int_as_float(0), 0.0f);
        if (lane == 0) g_nnz[col] = tot4;
    } else {
        // ---- coefficient transform: warp = (tree, tdim) ----
        const int cb = blockIdx.x - 192;
        const int n  = cb * 4 + (warp >> 1);
        const int t  = warp & 1;
        float r0 = resp[(n * 2 + t) * 64 + lane];
        float r1 = resp[(n * 2 + t) * 64 + 32 + lane];
        #pragma unroll
        for (int d = 0; d < 5; d++) {
            int m = 1 << d;
            float o0 = __shfl_xor_sync(~0u, r0, m);
            float o1 = __shfl_xor_sync(~0u, r1, m);
            bool hi = (lane >> d) & 1;
            r0 = hi ? (o0 - r0) : o0;   // bit=0 slot: const=A1; bit=1: lin=A0-A1
            r1 = hi ? (o1 - r1) : o1;
        }
        { float tmp = r0; r0 = r1; r1 = tmp - r1; }   // d=5 across regs
        g_coef[(n * 64 + lane)      * 2 + t] = r0;
        g_coef[(n * 64 + 32 + lane) * 2 + t] = r1;
    }
}

// ---------------------------------------------------------------------------
// Main kernel: block = (tree group of 32, batch tile of 64 rows), 512 threads.
// sub = tid>>5 owns 2 trees; lane owns a batch row-pair (b0=2*lane, b1=+1).
// 2 CTAs/SM (smem 108 KB, regs capped 64) -> single wave of 256 blocks.
// ---------------------------------------------------------------------------
__global__ void __launch_bounds__(512, 2) odt_main(
    const float* __restrict__ inputs,
    const float* __restrict__ thr,
    const float* __restrict__ logT,
    float* __restrict__ out)
{
    extern __shared__ __align__(16) char smem[];
    float*  s_in    = (float*) smem;                 // [256][66]
    float4* s_pack4 = (float4*)(smem + OFF_PACK);    // [192][8] f4 (=16 f2)
    float4* s_coef4 = (float4*)(smem + OFF_COEF);    // [32][32] f4
    int*    s_nnz   = (int*)   (smem + OFF_NNZ);     // [192]
    float2* s_th    = (float2*)(smem + OFF_TH);      // [192]

    const int tid  = threadIdx.x;
    const int lane = tid & 31;
    const int sub  = tid >> 5;
    const int grp  = blockIdx.x;          // 0..7
    const int tileB = blockIdx.y * 64;    // batch tile base
    const int nBase = grp * 32;
    const int colBase = nBase * DEPTH;    // grp*192

    // stage input tile [256 i][64 b] transposed, pad 66
    #pragma unroll
    for (int e = 0; e < 32; e++) {
        int linear = e * 512 + tid;
        int i = linear & 255, b = linear >> 8;
        s_in[i * TPAD + b] = inputs[(tileB + b) * INPUT_DIM + i];
    }
    // stage packs (first PCAP=16 entries per column): 192*8 = 1536 float4
    const float4* gp4 = (const float4*)g_pack;
    #pragma unroll
    for (int q = 0; q < 3; q++) {
        int idx = q * 512 + tid;
        int cl = idx >> 3, j = idx & 7;
        s_pack4[cl * 8 + j] = gp4[(colBase + cl) * (MAXNZ / 2) + j];
    }
    // stage coefficients: 1024 float4
    const float4* gc4 = (const float4*)g_coef;
    #pragma unroll
    for (int e = 0; e < 2; e++) {
        int idx = e * 512 + tid;
        s_coef4[idx] = gc4[nBase * 32 + idx];
    }
    // nnz + thresholds
    if (tid < 192) {
        int gcol = colBase + tid;
        s_nnz[tid] = g_nnz[gcol];
        s_th[tid]  = make_float2(thr[gcol], 0.5f * expf(-logT[gcol]));
    }
    __syncthreads();

    float2 res[2][2];   // [k][row]

    #pragma unroll
    for (int k = 0; k < 2; k++) {
        const int nL = sub * 2 + k;

        // p values for both rows
        float2 pp0[DEPTH], pp1[DEPTH];
        #pragma unroll
        for (int d = 0; d < DEPTH; d++) {
            const int colL = nL * DEPTH + d;
            const int nn = s_nnz[colL];
            const int nns = nn < PCAP ? nn : PCAP;
            float2 acc = make_float2(0.0f, 0.0f);
            const float4* pk = s_pack4 + colL * 8;
            for (int j = 0; j < nns; j += 4) {
                float4 a = pk[j >> 1];
                float4 b = pk[(j >> 1) + 1];
                int i0 = __float_as_int(a.x), i1 = __float_as_int(a.z);
                int i2 = __float_as_int(b.x), i3 = __float_as_int(b.z);
                float2 x0 = *(const float2*)(s_in + i0 * TPAD + 2 * lane);
                float2 x1 = *(const float2*)(s_in + i1 * TPAD + 2 * lane);
                float2 x2 = *(const float2*)(s_in + i2 * TPAD + 2 * lane);
                float2 x3 = *(const float2*)(s_in + i3 * TPAD + 2 * lane);
                acc = fma2(x0, make_float2(a.y, a.y), acc);
                acc = fma2(x1, make_float2(a.w, a.w), acc);
                acc = fma2(x2, make_float2(b.y, b.y), acc);
                acc = fma2(x3, make_float2(b.w, b.w), acc);
            }
            // rare fallback: support > PCAP
            for (int j = PCAP; j < nn; j += 4) {
                const float2* gq = g_pack + (size_t)(colBase + colL) * MAXNZ + j;
                #pragma unroll
                for (int u = 0; u < 4; u++) {
                    float2 q = __ldg(gq + u);
                    int ii = __float_as_int(q.x);
                    float2 x = *(const float2*)(s_in + ii * TPAD + 2 * lane);
                    acc = fma2(x, make_float2(q.y, q.y), acc);
                }
            }
            float2 th = s_th[colL];
            float pA = fminf(fmaxf(fmaf(acc.x - th.x, th.y, 0.5f), 0.0f), 1.0f);
            float pB = fminf(fmaxf(fmaf(acc.y - th.x, th.y, 0.5f), 0.0f), 1.0f);
            pp0[d] = make_float2(pA, pA);
            pp1[d] = make_float2(pB, pB);
        }

        // multilinear evaluation, tdims packed, both rows share coef loads
        const float4* cf = s_coef4 + nL * 32;
        float2 w0[8], w1[8];
        #pragma unroll
        for (int j = 0; j < 8; j++) {
            float2 v0a, v0b, v1a, v1b;
            {
                float4 c0 = cf[4 * j + 0], c1 = cf[4 * j + 1];
                float2 lo0 = make_float2(c0.x, c0.y), hi0 = make_float2(c0.z, c0.w);
                float2 lo1 = make_float2(c1.x, c1.y), hi1 = make_float2(c1.z, c1.w);
                float2 u0r0 = fma2(pp0[0], hi0, lo0);
                float2 u0r1 = fma2(pp1[0], hi0, lo0);
                float2 u1r0 = fma2(pp0[0], hi1, lo1);
                float2 u1r1 = fma2(pp1[0], hi1, lo1);
                v0a = fma2(pp0[1], u1r0, u0r0);
                v1a = fma2(pp1[1], u1r1, u0r1);
            }
            {
                float4 c2 = cf[4 * j + 2], c3 = cf[4 * j + 3];
                float2 lo2 = make_float2(c2.x, c2.y), hi2 = make_float2(c2.z, c2.w);
                float2 lo3 = make_float2(c3.x, c3.y), hi3 = make_float2(c3.z, c3.w);
                float2 u2r0 = fma2(pp0[0], hi2, lo2);
                float2 u2r1 = fma2(pp1[0], hi2, lo2);
                float2 u3r0 = fma2(pp0[0], hi3, lo3);
                float2 u3r1 = fma2(pp1[0], hi3, lo3);
                v0b = fma2(pp0[1], u3r0, u2r0);
                v1b = fma2(pp1[1], u3r1, u2r1);
            }
            w0[j] = fma2(pp0[2], v0b, v0a);
            w1[j] = fma2(pp1[2], v1b, v1a);
        }
        float2 x0[4], x1[4];
        #pragma unroll
        for (int j = 0; j < 4; j++) {
            x0[j] = fma2(pp0[3], w0[2 * j + 1], w0[2 * j]);
            x1[j] = fma2(pp1[3], w1[2 * j + 1], w1[2 * j]);
        }
        float2 y00 = fma2(pp0[4], x0[1], x0[0]);
        float2 y01 = fma2(pp0[4], x0[3], x0[2]);
        float2 y10 = fma2(pp1[4], x1[1], x1[0]);
        float2 y11 = fma2(pp1[4], x1[3], x1[2]);
        res[k][0] = fma2(pp0[5], y01, y00);
        res[k][1] = fma2(pp1[5], y11, y10);
    }

    // store: 4 consecutive trees' (t0,t1) per row -> 16B aligned STG.128
    const int b0 = tileB + 2 * lane;
    float* o0 = out + (size_t)b0 * OUTW + grp * 64 + sub * 4;
    float* o1 = o0 + OUTW;
    *(float4*)o0 = make_float4(res[0][0].x, res[0][0].y, res[1][0].x, res[1][0].y);
    *(float4*)o1 = make_float4(res[0][1].x, res[0][1].y, res[1][1].x, res[1][1].y);
}

// ---------------------------------------------------------------------------
extern "C" void kernel_launch(void* const* d_in, const int* in_sizes, int n_in,
                              void* d_out, int out_size) {
    const float* inputs = (const float*)d_in[0];
    const float* fsl    = (const float*)d_in[1];
    const float* thr    = (const float*)d_in[2];
    const float* logT   = (const float*)d_in[3];
    const float* resp   = (const float*)d_in[4];
    float* out = (float*)d_out;

    cudaFuncSetAttribute(odt_main, cudaFuncAttributeMaxDynamicSharedMemorySize,
                         ODT_SMEM);

    prep_kernel<<<256, 256>>>(fsl, resp);
    odt_main<<<dim3(8, 32), 512, ODT_SMEM>>>(inputs, thr, logT, out);
}